// round 2
// baseline (speedup 1.0000x reference)
#include <cuda_runtime.h>
#include <cuda_bf16.h>
#include <math.h>

// Problem constants (B=1, S=2048, E=2048, D=64, H=32, KVH=8, group=4)
#define S_LEN 2048
#define E_DIM 2048
#define HEADS 32
#define KVH 8
#define HDIM 64
#define KV_DIM (KVH * HDIM)   // 512

// Scratch (device globals: allocation inside kernel_launch is forbidden)
__device__ float g_q[S_LEN * E_DIM];      // [S, H, D]
__device__ float g_k[S_LEN * KV_DIM];     // [S, KVH, D]
__device__ float g_v[S_LEN * KV_DIM];     // [S, KVH, D]
__device__ float g_att[S_LEN * E_DIM];    // [S, H, D]

// ---------------------------------------------------------------------------
// GEMM: C[M,N] = A[M,K] @ B[N,K]^T   (both operands K-contiguous, "NT")
// 64x64 tile, BK=16, 256 threads, 4x4 microtile.
// ---------------------------------------------------------------------------
#define BM 64
#define BN 64
#define BK 16

__global__ __launch_bounds__(256) void gemm_nt(
    const float* __restrict__ A, const float* __restrict__ B,
    float* __restrict__ C, int M, int N, int K)
{
    __shared__ float As[BK][BM];
    __shared__ float Bs[BK][BN];

    const int tid = threadIdx.x;
    const int tx = tid % 16;
    const int ty = tid / 16;
    const int bm = blockIdx.y * BM;
    const int bn = blockIdx.x * BN;

    const int lk = tid % BK;   // 0..15
    const int lr = tid / BK;   // 0..15

    float acc[4][4] = {};

    for (int k0 = 0; k0 < K; k0 += BK) {
        #pragma unroll
        for (int i = 0; i < 4; i++) {
            As[lk][lr + 16 * i] = A[(size_t)(bm + lr + 16 * i) * K + k0 + lk];
            Bs[lk][lr + 16 * i] = B[(size_t)(bn + lr + 16 * i) * K + k0 + lk];
        }
        __syncthreads();

        #pragma unroll
        for (int kk = 0; kk < BK; kk++) {
            float a[4], b[4];
            #pragma unroll
            for (int i = 0; i < 4; i++) a[i] = As[kk][ty * 4 + i];
            #pragma unroll
            for (int j = 0; j < 4; j++) b[j] = Bs[kk][tx * 4 + j];
            #pragma unroll
            for (int i = 0; i < 4; i++)
                #pragma unroll
                for (int j = 0; j < 4; j++)
                    acc[i][j] += a[i] * b[j];
        }
        __syncthreads();
    }

    #pragma unroll
    for (int i = 0; i < 4; i++)
        #pragma unroll
        for (int j = 0; j < 4; j++)
            C[(size_t)(bm + ty * 4 + i) * N + bn + tx * 4 + j] = acc[i][j];
}

// ---------------------------------------------------------------------------
// RoPE, in place. t: [S, H, D=64], cos/sin: [S, 64] with halves duplicated.
// grid = S, block = H*32 (one thread per (head, d<32)).
// ---------------------------------------------------------------------------
__global__ void rope_kernel(float* __restrict__ t,
                            const float* __restrict__ cosb,
                            const float* __restrict__ sinb, int H)
{
    const int s = blockIdx.x;
    const int h = threadIdx.x / 32;
    const int d = threadIdx.x % 32;
    float* p = t + ((size_t)s * H + h) * HDIM;
    const float c  = cosb[s * HDIM + d];
    const float sn = sinb[s * HDIM + d];
    const float a = p[d];
    const float b = p[d + 32];
    p[d]      = a * c - b * sn;
    p[d + 32] = b * c + a * sn;
}

// ---------------------------------------------------------------------------
// Flash-style causal attention.
// Q: [S, H, 64], K/V: [S, KVH, 64], O: [S, H, 64]
// grid = (S/64, H), block = 256 (16x16). BQ=64 q-rows, BKT=32 key-rows/iter.
// Thread owns score tile 4x2 (rows 4*ty.., cols 2*tx..) and O tile 4x4.
// ---------------------------------------------------------------------------
#define BQ 64
#define BKT 32

__global__ __launch_bounds__(256) void attn_kernel(
    const float* __restrict__ Q, const float* __restrict__ K,
    const float* __restrict__ V, float* __restrict__ O)
{
    const int qb  = blockIdx.x;
    const int h   = blockIdx.y;
    const int kvh = h >> 2;            // group = 4

    __shared__ float Qs[BQ][HDIM + 1];
    __shared__ float Ks[BKT][HDIM + 1];
    __shared__ float Vs[BKT][HDIM + 1];
    __shared__ float Ps[BQ][BKT + 1];

    const int tid = threadIdx.x;
    const int tx = tid % 16;
    const int ty = tid / 16;

    // Load Q tile (coalesced over d)
    #pragma unroll
    for (int i = 0; i < 16; i++) {
        int idx = tid + 256 * i;               // 0..4095
        int r = idx / HDIM, c = idx % HDIM;
        Qs[r][c] = Q[((size_t)(qb * BQ + r) * HEADS + h) * HDIM + c];
    }

    float m[4], l[4], o[4][4];
    #pragma unroll
    for (int i = 0; i < 4; i++) {
        m[i] = -1e30f; l[i] = 0.f;
        #pragma unroll
        for (int j = 0; j < 4; j++) o[i][j] = 0.f;
    }

    const float scale = 0.125f;  // 1/sqrt(64)
    const int nkb = 2 * qb + 2;  // key blocks needed for causal coverage

    for (int kb = 0; kb < nkb; kb++) {
        // Load K/V tiles: 32x64 = 2048 elems, 8 per thread
        #pragma unroll
        for (int i = 0; i < 8; i++) {
            int idx = tid + 256 * i;
            int r = idx / HDIM, c = idx % HDIM;
            size_t g = ((size_t)(kb * BKT + r) * KVH + kvh) * HDIM + c;
            Ks[r][c] = K[g];
            Vs[r][c] = V[g];
        }
        __syncthreads();

        // Scores: 4 rows x 2 cols per thread
        float sc[4][2] = {};
        #pragma unroll
        for (int d = 0; d < HDIM; d++) {
            float a[4], b[2];
            #pragma unroll
            for (int i = 0; i < 4; i++) a[i] = Qs[ty * 4 + i][d];
            #pragma unroll
            for (int j = 0; j < 2; j++) b[j] = Ks[tx * 2 + j][d];
            #pragma unroll
            for (int i = 0; i < 4; i++)
                #pragma unroll
                for (int j = 0; j < 2; j++)
                    sc[i][j] += a[i] * b[j];
        }

        // Scale + causal mask
        #pragma unroll
        for (int i = 0; i < 4; i++) {
            int grow = qb * BQ + ty * 4 + i;
            #pragma unroll
            for (int j = 0; j < 2; j++) {
                int gcol = kb * BKT + tx * 2 + j;
                sc[i][j] = (gcol <= grow) ? sc[i][j] * scale : -1e30f;
            }
        }

        // Online softmax per row (rows shared by 16 consecutive lanes)
        #pragma unroll
        for (int i = 0; i < 4; i++) {
            float rmax = fmaxf(sc[i][0], sc[i][1]);
            #pragma unroll
            for (int off = 8; off > 0; off >>= 1)
                rmax = fmaxf(rmax, __shfl_xor_sync(0xffffffffu, rmax, off));
            float mnew = fmaxf(m[i], rmax);
            float alpha = __expf(m[i] - mnew);
            float p0 = __expf(sc[i][0] - mnew);
            float p1 = __expf(sc[i][1] - mnew);
            float rsum = p0 + p1;
            #pragma unroll
            for (int off = 8; off > 0; off >>= 1)
                rsum += __shfl_xor_sync(0xffffffffu, rsum, off);
            l[i] = l[i] * alpha + rsum;
            m[i] = mnew;
            #pragma unroll
            for (int j = 0; j < 4; j++) o[i][j] *= alpha;
            Ps[ty * 4 + i][tx * 2 + 0] = p0;
            Ps[ty * 4 + i][tx * 2 + 1] = p1;
        }
        __syncthreads();

        // O += P @ V : 4x4 per thread over K=32
        #pragma unroll
        for (int kk = 0; kk < BKT; kk++) {
            float a[4], b[4];
            #pragma unroll
            for (int i = 0; i < 4; i++) a[i] = Ps[ty * 4 + i][kk];
            #pragma unroll
            for (int j = 0; j < 4; j++) b[j] = Vs[kk][tx * 4 + j];
            #pragma unroll
            for (int i = 0; i < 4; i++)
                #pragma unroll
                for (int j = 0; j < 4; j++)
                    o[i][j] += a[i] * b[j];
        }
        __syncthreads();
    }

    // Normalize and store
    #pragma unroll
    for (int i = 0; i < 4; i++) {
        float inv = 1.0f / l[i];
        int grow = qb * BQ + ty * 4 + i;
        #pragma unroll
        for (int j = 0; j < 4; j++)
            O[((size_t)grow * HEADS + h) * HDIM + tx * 4 + j] = o[i][j] * inv;
    }
}

// ---------------------------------------------------------------------------
// Launch
// Inputs: 0:x 1:Wq 2:Wk 3:Wv 4:Wo 5:cos 6:sin 7:attn_mask 8:last_pos
// ---------------------------------------------------------------------------
extern "C" void kernel_launch(void* const* d_in, const int* in_sizes, int n_in,
                              void* d_out, int out_size)
{
    const float* x   = (const float*)d_in[0];
    const float* Wq  = (const float*)d_in[1];
    const float* Wk  = (const float*)d_in[2];
    const float* Wv  = (const float*)d_in[3];
    const float* Wo  = (const float*)d_in[4];
    const float* cosb = (const float*)d_in[5];
    const float* sinb = (const float*)d_in[6];
    float* out = (float*)d_out;

    float *q, *k, *v, *att;
    cudaGetSymbolAddress((void**)&q,   g_q);
    cudaGetSymbolAddress((void**)&k,   g_k);
    cudaGetSymbolAddress((void**)&v,   g_v);
    cudaGetSymbolAddress((void**)&att, g_att);

    dim3 blk(256);

    // QKV projections
    gemm_nt<<<dim3(E_DIM / BN,  S_LEN / BM), blk>>>(x, Wq, q, S_LEN, E_DIM,  E_DIM);
    gemm_nt<<<dim3(KV_DIM / BN, S_LEN / BM), blk>>>(x, Wk, k, S_LEN, KV_DIM, E_DIM);
    gemm_nt<<<dim3(KV_DIM / BN, S_LEN / BM), blk>>>(x, Wv, v, S_LEN, KV_DIM, E_DIM);

    // RoPE on q (H=32) and k (KVH=8)
    rope_kernel<<<S_LEN, HEADS * 32>>>(q, cosb, sinb, HEADS);
    rope_kernel<<<S_LEN, KVH * 32>>>(k, cosb, sinb, KVH);

    // Causal GQA attention
    attn_kernel<<<dim3(S_LEN / BQ, HEADS), blk>>>(q, k, v, att);

    // Output projection
    gemm_nt<<<dim3(E_DIM / BN, S_LEN / BM), blk>>>(att, Wo, out, S_LEN, E_DIM, E_DIM);
}

// round 4
// speedup vs baseline: 2.1696x; 2.1696x over previous
#include <cuda_runtime.h>
#include <cuda_bf16.h>
#include <cstdint>
#include <math.h>

// Problem constants (B=1, S=2048, E=2048, D=64, H=32, KVH=8, group=4)
#define S_LEN 2048
#define E_DIM 2048
#define HEADS 32
#define KVH 8
#define HDIM 64
#define KV_DIM (KVH * HDIM)   // 512
#define KEXP (3 * E_DIM)      // 6144 : split-bf16 expanded K

// ---------------------------------------------------------------------------
// Scratch (device globals: runtime allocation is forbidden)
// ---------------------------------------------------------------------------
__device__ float g_q[S_LEN * E_DIM];      // [S, H, D]
__device__ float g_k[S_LEN * KV_DIM];     // [S, KVH, D]
__device__ float g_v[S_LEN * KV_DIM];     // [S, KVH, D]
__device__ float g_att[S_LEN * E_DIM];    // [S, H, D]

__device__ __nv_bfloat16 g_xexp[S_LEN * KEXP];
__device__ __nv_bfloat16 g_wqexp[E_DIM * KEXP];
__device__ __nv_bfloat16 g_wkexp[KV_DIM * KEXP];
__device__ __nv_bfloat16 g_wvexp[KV_DIM * KEXP];
__device__ __nv_bfloat16 g_woexp[E_DIM * KEXP];
__device__ __nv_bfloat16 g_attexp[S_LEN * KEXP];

__device__ __forceinline__ uint32_t smem_u32(const void* p) {
    uint32_t a;
    asm("{ .reg .u64 t; cvta.to.shared.u64 t, %1; cvt.u32.u64 %0, t; }"
        : "=r"(a) : "l"(p));
    return a;
}

// ---------------------------------------------------------------------------
// split-bf16 expansion: fp32 [rows,K] -> bf16 [rows,3K]
// modeB=0 (A side): [hi | hi | lo];  modeB=1 (B side): [hi | lo | hi]
// C = Aexp @ Bexp^T = ah*bh + ah*bl + al*bh   (drops al*bl ~ 2^-18)
// ---------------------------------------------------------------------------
__global__ void split_bf16(const float* __restrict__ in, __nv_bfloat16* __restrict__ out,
                           int rows, int K, int modeB)
{
    int n = rows * K;
    for (int idx = blockIdx.x * blockDim.x + threadIdx.x; idx < n;
         idx += gridDim.x * blockDim.x) {
        int r = idx / K, k = idx - r * K;
        float v = in[idx];
        __nv_bfloat16 h = __float2bfloat16(v);
        __nv_bfloat16 l = __float2bfloat16(v - __bfloat162float(h));
        __nv_bfloat16* o = out + (size_t)r * (3 * K);
        if (modeB) { o[k] = h; o[K + k] = l; o[2 * K + k] = h; }
        else       { o[k] = h; o[K + k] = h; o[2 * K + k] = l; }
    }
}

// ---------------------------------------------------------------------------
// bf16 GEMM via mma.sync (HMMA): C[M,N] fp32 = A[M,K'] @ B[N,K']^T
// Block 128x128, BK=32, 8 warps (warp tile 64x32), cp.async double buffer.
// Smem rows have 80B stride (40 bf16) -> conflict-free ldmatrix.
// ---------------------------------------------------------------------------
#define GBK 32
#define ROWB 80          // bytes per smem row
#define TILEB (128 * ROWB)   // 10240 B per buffer

__global__ __launch_bounds__(256) void mma_gemm(
    const __nv_bfloat16* __restrict__ A, const __nv_bfloat16* __restrict__ B,
    float* __restrict__ C, int M, int N, int K)
{
    __shared__ __align__(16) uint8_t sm[4 * TILEB];  // A0 A1 B0 B1
    const uint32_t sb = smem_u32(sm);

    const int tid  = threadIdx.x;
    const int lane = tid & 31;
    const int wid  = tid >> 5;
    const int wm   = wid & 1;        // 0..1 : 64-row slab
    const int wn   = wid >> 1;       // 0..3 : 32-col slab
    const int bm   = blockIdx.y * 128;
    const int bn   = blockIdx.x * 128;

    float acc[4][4][4];
    #pragma unroll
    for (int i = 0; i < 4; i++)
        #pragma unroll
        for (int j = 0; j < 4; j++)
            #pragma unroll
            for (int c = 0; c < 4; c++) acc[i][j][c] = 0.f;

    // ldmatrix per-lane byte offsets (within a buffer)
    uint32_t aoff[4], boff[2];
    {
        const int l7 = lane & 7;
        const int rA = ((lane >> 3) & 1) * 8;     // row add for A lanes
        const int kA = ((lane >> 4) & 1) * 16;    // k-half byte add for A
        #pragma unroll
        for (int mb = 0; mb < 4; mb++) {
            int row = wm * 64 + mb * 16 + l7 + rA;
            aoff[mb] = (uint32_t)(row * ROWB + kA);
        }
        const int rB = ((lane >> 4) & 1) * 8;     // n add for B lanes
        const int kB = ((lane >> 3) & 1) * 16;    // k-half byte add for B
        #pragma unroll
        for (int p = 0; p < 2; p++) {
            int row = wn * 32 + p * 16 + l7 + rB;
            boff[p] = (uint32_t)(row * ROWB + kB);
        }
    }

    const int NKC = K / GBK;

    // cp.async tile loader: 128 rows x 64B (GBK bf16), 4 x 16B chunks per row
    auto load_tiles = [&](int k0, int which) {
        uint32_t da = sb + which * TILEB;
        uint32_t db = sb + (2 + which) * TILEB;
        #pragma unroll
        for (int i = 0; i < 2; i++) {
            int c  = tid + 256 * i;      // 0..511
            int r  = c >> 2;
            int cc = c & 3;
            uint32_t dsta = da + r * ROWB + cc * 16;
            uint32_t dstb = db + r * ROWB + cc * 16;
            const __nv_bfloat16* sa = A + (size_t)(bm + r) * K + k0 + cc * 8;
            const __nv_bfloat16* sbp = B + (size_t)(bn + r) * K + k0 + cc * 8;
            asm volatile("cp.async.cg.shared.global [%0], [%1], 16;" :: "r"(dsta), "l"(sa) : "memory");
            asm volatile("cp.async.cg.shared.global [%0], [%1], 16;" :: "r"(dstb), "l"(sbp) : "memory");
        }
    };

    load_tiles(0, 0);
    asm volatile("cp.async.commit_group;" ::: "memory");
    load_tiles(GBK, 1);
    asm volatile("cp.async.commit_group;" ::: "memory");

    for (int kc = 0; kc < NKC; kc++) {
        asm volatile("cp.async.wait_group 1;" ::: "memory");
        __syncthreads();

        const int which = kc & 1;
        const uint32_t abuf = sb + which * TILEB;
        const uint32_t bbuf = sb + (2 + which) * TILEB;

        #pragma unroll
        for (int ks = 0; ks < 2; ks++) {
            uint32_t af[4][4], bf[4][2];
            #pragma unroll
            for (int mb = 0; mb < 4; mb++) {
                uint32_t addr = abuf + aoff[mb] + ks * 32;
                asm volatile("ldmatrix.sync.aligned.m8n8.x4.shared.b16 {%0,%1,%2,%3}, [%4];"
                             : "=r"(af[mb][0]), "=r"(af[mb][1]), "=r"(af[mb][2]), "=r"(af[mb][3])
                             : "r"(addr));
            }
            #pragma unroll
            for (int p = 0; p < 2; p++) {
                uint32_t addr = bbuf + boff[p] + ks * 32;
                asm volatile("ldmatrix.sync.aligned.m8n8.x4.shared.b16 {%0,%1,%2,%3}, [%4];"
                             : "=r"(bf[2 * p][0]), "=r"(bf[2 * p][1]),
                               "=r"(bf[2 * p + 1][0]), "=r"(bf[2 * p + 1][1])
                             : "r"(addr));
            }
            #pragma unroll
            for (int mb = 0; mb < 4; mb++)
                #pragma unroll
                for (int nb = 0; nb < 4; nb++) {
                    asm volatile(
                        "mma.sync.aligned.m16n8k16.row.col.f32.bf16.bf16.f32 "
                        "{%0,%1,%2,%3}, {%4,%5,%6,%7}, {%8,%9}, {%0,%1,%2,%3};"
                        : "+f"(acc[mb][nb][0]), "+f"(acc[mb][nb][1]),
                          "+f"(acc[mb][nb][2]), "+f"(acc[mb][nb][3])
                        : "r"(af[mb][0]), "r"(af[mb][1]), "r"(af[mb][2]), "r"(af[mb][3]),
                          "r"(bf[nb][0]), "r"(bf[nb][1]));
                }
        }

        __syncthreads();
        if (kc + 2 < NKC) {
            load_tiles((kc + 2) * GBK, which);
        }
        asm volatile("cp.async.commit_group;" ::: "memory");
    }

    // Epilogue
    const int g  = lane >> 2;
    const int tc = (lane & 3) * 2;
    #pragma unroll
    for (int mb = 0; mb < 4; mb++) {
        const int row0 = bm + wm * 64 + mb * 16 + g;
        #pragma unroll
        for (int nb = 0; nb < 4; nb++) {
            const int col = bn + wn * 32 + nb * 8 + tc;
            *(float2*)&C[(size_t)row0 * N + col]       = make_float2(acc[mb][nb][0], acc[mb][nb][1]);
            *(float2*)&C[(size_t)(row0 + 8) * N + col] = make_float2(acc[mb][nb][2], acc[mb][nb][3]);
        }
    }
}

// ---------------------------------------------------------------------------
// RoPE, in place. t: [S, H, D=64], cos/sin: [S, 64] halves duplicated.
// ---------------------------------------------------------------------------
__global__ void rope_kernel(float* __restrict__ t,
                            const float* __restrict__ cosb,
                            const float* __restrict__ sinb, int H)
{
    const int s = blockIdx.x;
    const int h = threadIdx.x / 32;
    const int d = threadIdx.x % 32;
    float* p = t + ((size_t)s * H + h) * HDIM;
    const float c  = cosb[s * HDIM + d];
    const float sn = sinb[s * HDIM + d];
    const float a = p[d];
    const float b = p[d + 32];
    p[d]      = a * c - b * sn;
    p[d + 32] = b * c + a * sn;
}

// ---------------------------------------------------------------------------
// Flash-style causal GQA attention (fp32). Unchanged from R1.
// ---------------------------------------------------------------------------
#define BQ 64
#define BKT 32

__global__ __launch_bounds__(256) void attn_kernel(
    const float* __restrict__ Q, const float* __restrict__ K,
    const float* __restrict__ V, float* __restrict__ O)
{
    const int qb  = blockIdx.x;
    const int h   = blockIdx.y;
    const int kvh = h >> 2;            // group = 4

    __shared__ float Qs[BQ][HDIM + 1];
    __shared__ float Ks[BKT][HDIM + 1];
    __shared__ float Vs[BKT][HDIM + 1];
    __shared__ float Ps[BQ][BKT + 1];

    const int tid = threadIdx.x;
    const int tx = tid % 16;
    const int ty = tid / 16;

    #pragma unroll
    for (int i = 0; i < 16; i++) {
        int idx = tid + 256 * i;
        int r = idx / HDIM, c = idx % HDIM;
        Qs[r][c] = Q[((size_t)(qb * BQ + r) * HEADS + h) * HDIM + c];
    }

    float m[4], l[4], o[4][4];
    #pragma unroll
    for (int i = 0; i < 4; i++) {
        m[i] = -1e30f; l[i] = 0.f;
        #pragma unroll
        for (int j = 0; j < 4; j++) o[i][j] = 0.f;
    }

    const float scale = 0.125f;
    const int nkb = 2 * qb + 2;

    for (int kb = 0; kb < nkb; kb++) {
        #pragma unroll
        for (int i = 0; i < 8; i++) {
            int idx = tid + 256 * i;
            int r = idx / HDIM, c = idx % HDIM;
            size_t g = ((size_t)(kb * BKT + r) * KVH + kvh) * HDIM + c;
            Ks[r][c] = K[g];
            Vs[r][c] = V[g];
        }
        __syncthreads();

        float sc[4][2] = {};
        #pragma unroll
        for (int d = 0; d < HDIM; d++) {
            float a[4], b[2];
            #pragma unroll
            for (int i = 0; i < 4; i++) a[i] = Qs[ty * 4 + i][d];
            #pragma unroll
            for (int j = 0; j < 2; j++) b[j] = Ks[tx * 2 + j][d];
            #pragma unroll
            for (int i = 0; i < 4; i++)
                #pragma unroll
                for (int j = 0; j < 2; j++)
                    sc[i][j] += a[i] * b[j];
        }

        #pragma unroll
        for (int i = 0; i < 4; i++) {
            int grow = qb * BQ + ty * 4 + i;
            #pragma unroll
            for (int j = 0; j < 2; j++) {
                int gcol = kb * BKT + tx * 2 + j;
                sc[i][j] = (gcol <= grow) ? sc[i][j] * scale : -1e30f;
            }
        }

        #pragma unroll
        for (int i = 0; i < 4; i++) {
            float rmax = fmaxf(sc[i][0], sc[i][1]);
            #pragma unroll
            for (int off = 8; off > 0; off >>= 1)
                rmax = fmaxf(rmax, __shfl_xor_sync(0xffffffffu, rmax, off));
            float mnew = fmaxf(m[i], rmax);
            float alpha = __expf(m[i] - mnew);
            float p0 = __expf(sc[i][0] - mnew);
            float p1 = __expf(sc[i][1] - mnew);
            float rsum = p0 + p1;
            #pragma unroll
            for (int off = 8; off > 0; off >>= 1)
                rsum += __shfl_xor_sync(0xffffffffu, rsum, off);
            l[i] = l[i] * alpha + rsum;
            m[i] = mnew;
            #pragma unroll
            for (int j = 0; j < 4; j++) o[i][j] *= alpha;
            Ps[ty * 4 + i][tx * 2 + 0] = p0;
            Ps[ty * 4 + i][tx * 2 + 1] = p1;
        }
        __syncthreads();

        #pragma unroll
        for (int kk = 0; kk < BKT; kk++) {
            float a[4], b[4];
            #pragma unroll
            for (int i = 0; i < 4; i++) a[i] = Ps[ty * 4 + i][kk];
            #pragma unroll
            for (int j = 0; j < 4; j++) b[j] = Vs[kk][tx * 4 + j];
            #pragma unroll
            for (int i = 0; i < 4; i++)
                #pragma unroll
                for (int j = 0; j < 4; j++)
                    o[i][j] += a[i] * b[j];
        }
        __syncthreads();
    }

    #pragma unroll
    for (int i = 0; i < 4; i++) {
        float inv = 1.0f / l[i];
        int grow = qb * BQ + ty * 4 + i;
        #pragma unroll
        for (int j = 0; j < 4; j++)
            O[((size_t)grow * HEADS + h) * HDIM + tx * 4 + j] = o[i][j] * inv;
    }
}

// ---------------------------------------------------------------------------
// Launch. Inputs: 0:x 1:Wq 2:Wk 3:Wv 4:Wo 5:cos 6:sin 7:attn_mask 8:last_pos
// ---------------------------------------------------------------------------
extern "C" void kernel_launch(void* const* d_in, const int* in_sizes, int n_in,
                              void* d_out, int out_size)
{
    const float* x    = (const float*)d_in[0];
    const float* Wq   = (const float*)d_in[1];
    const float* Wk   = (const float*)d_in[2];
    const float* Wv   = (const float*)d_in[3];
    const float* Wo   = (const float*)d_in[4];
    const float* cosb = (const float*)d_in[5];
    const float* sinb = (const float*)d_in[6];
    float* out = (float*)d_out;

    float *q, *k, *v, *att;
    __nv_bfloat16 *xe, *wqe, *wke, *wve, *woe, *atte;
    cudaGetSymbolAddress((void**)&q,    g_q);
    cudaGetSymbolAddress((void**)&k,    g_k);
    cudaGetSymbolAddress((void**)&v,    g_v);
    cudaGetSymbolAddress((void**)&att,  g_att);
    cudaGetSymbolAddress((void**)&xe,   g_xexp);
    cudaGetSymbolAddress((void**)&wqe,  g_wqexp);
    cudaGetSymbolAddress((void**)&wke,  g_wkexp);
    cudaGetSymbolAddress((void**)&wve,  g_wvexp);
    cudaGetSymbolAddress((void**)&woe,  g_woexp);
    cudaGetSymbolAddress((void**)&atte, g_attexp);

    // Split-bf16 expansion
    split_bf16<<<4096, 256>>>(x,  xe,  S_LEN,  E_DIM, 0);
    split_bf16<<<4096, 256>>>(Wq, wqe, E_DIM,  E_DIM, 1);
    split_bf16<<<1024, 256>>>(Wk, wke, KV_DIM, E_DIM, 1);
    split_bf16<<<1024, 256>>>(Wv, wve, KV_DIM, E_DIM, 1);
    split_bf16<<<4096, 256>>>(Wo, woe, E_DIM,  E_DIM, 1);

    // Projections (HMMA)
    mma_gemm<<<dim3(E_DIM / 128,  S_LEN / 128), 256>>>(xe, wqe, q, S_LEN, E_DIM,  KEXP);
    mma_gemm<<<dim3(KV_DIM / 128, S_LEN / 128), 256>>>(xe, wke, k, S_LEN, KV_DIM, KEXP);
    mma_gemm<<<dim3(KV_DIM / 128, S_LEN / 128), 256>>>(xe, wve, v, S_LEN, KV_DIM, KEXP);

    // RoPE
    rope_kernel<<<S_LEN, HEADS * 32>>>(q, cosb, sinb, HEADS);
    rope_kernel<<<S_LEN, KVH * 32>>>(k, cosb, sinb, KVH);

    // Causal GQA attention (fp32)
    attn_kernel<<<dim3(S_LEN / BQ, HEADS), 256>>>(q, k, v, att);

    // Output projection (HMMA)
    split_bf16<<<4096, 256>>>(att, atte, S_LEN, E_DIM, 0);
    mma_gemm<<<dim3(E_DIM / 128, S_LEN / 128), 256>>>(atte, woe, out, S_LEN, E_DIM, KEXP);
}